// round 2
// baseline (speedup 1.0000x reference)
#include <cuda_runtime.h>

// BallPredictorGNN: output depends only on node N-1 ("ball").
// Sparse dependency-cone evaluation:
//   pass1: find edges into ball -> S1 sources
//   pass2: find edges into S1   -> layer-1 edge list + needed-feature mask
//   feat : h = x@W1 (+ per-head attention logits) for needed nodes only
//   agg1 : per-node layer-1 softmax-aggregate + W2 projection + layer-2 logits
//   final: layer-2 softmax-aggregate at ball + 2-layer MLP -> out[2]

#define NMAX      20480
#define FIN       128
#define H1C       256    // 4 heads * 64 ch
#define C2        64
#define SRCA_CAP  2048
#define EB_CAP    131072
#define DEG_CAP   512

__device__ int   g_need1[NMAX];          // node needs layer-1 output
__device__ int   g_needH[NMAX];          // node needs h = x@W1
__device__ int   g_cntA;                 // # graph edges into ball
__device__ int   g_cntB;                 // # graph edges into need1 nodes
__device__ int   g_srcA[SRCA_CAP];
__device__ int   g_srcB[EB_CAP];
__device__ int   g_dstB[EB_CAP];
__device__ float g_h  [(size_t)NMAX * H1C];
__device__ float g_as1[NMAX * 4];
__device__ float g_ad1[NMAX * 4];
__device__ float g_g  [(size_t)NMAX * C2];
__device__ float g_as2[NMAX];
__device__ float g_ad2[NMAX];

__global__ void k_reset(int N) {
    int i = blockIdx.x * blockDim.x + threadIdx.x;
    if (i < N) { g_need1[i] = 0; g_needH[i] = 0; }
    if (i == 0) { g_cntA = 0; g_cntB = 0; }
}

__global__ void k_pass1(const int* __restrict__ ei, int E, int ball, int N) {
    int e = blockIdx.x * blockDim.x + threadIdx.x;
    if (e == 0) { g_need1[ball] = 1; g_needH[ball] = 1; }
    if (e >= E) return;
    int dst = ei[E + e];
    if (dst == ball) {
        int src = ei[e];
        if ((unsigned)src >= (unsigned)N) return;   // defensive
        int p = atomicAdd(&g_cntA, 1);
        if (p < SRCA_CAP) g_srcA[p] = src;
        g_need1[src] = 1;   // plain stores: idempotent flags
        g_needH[src] = 1;
    }
}

__global__ void k_pass2(const int* __restrict__ ei, int E, int N) {
    int e = blockIdx.x * blockDim.x + threadIdx.x;
    if (e >= E) return;
    int dst = ei[E + e];
    if ((unsigned)dst >= (unsigned)N) return;       // defensive
    if (g_need1[dst]) {
        int src = ei[e];
        if ((unsigned)src >= (unsigned)N) return;   // defensive
        int p = atomicAdd(&g_cntB, 1);
        if (p < EB_CAP) { g_srcB[p] = src; g_dstB[p] = dst; }
        g_needH[src] = 1;
        g_needH[dst] = 1;
    }
}

// One block per node; compute h[v] = x[v] @ W1 (256 outputs) and the
// per-head attention logits alpha_src1/alpha_dst1. Only runs for needH nodes.
__global__ void k_feat(const float* __restrict__ x, const float* __restrict__ W1,
                       const float* __restrict__ a_src1, const float* __restrict__ a_dst1) {
    int v = blockIdx.x;
    if (!g_needH[v]) return;
    __shared__ float xs[FIN];
    __shared__ float hs[H1C];
    int t = threadIdx.x;
    if (t < FIN) xs[t] = x[(size_t)v * FIN + t];
    __syncthreads();
    float acc = 0.f;
#pragma unroll 8
    for (int f = 0; f < FIN; f++) acc += xs[f] * W1[f * H1C + t];
    hs[t] = acc;
    g_h[(size_t)v * H1C + t] = acc;
    __syncthreads();
    if (t < 8) {
        int hh = t & 3;
        const float* av = (t < 4) ? a_src1 : a_dst1;
        float s = 0.f;
        for (int c = 0; c < 64; c++) s += hs[hh * 64 + c] * av[hh * 64 + c];
        if (t < 4) g_as1[v * 4 + hh] = s; else g_ad1[v * 4 + hh] = s;
    }
}

// One block per node in need1: gather its incoming edges from the (src,dst)
// list, per-head stable softmax (incl. self-loop), aggregate h, add b1, relu,
// project with W2, compute layer-2 attention logits.
__global__ void k_agg1(const float* __restrict__ b1, const float* __restrict__ W2,
                       const float* __restrict__ a_src2, const float* __restrict__ a_dst2) {
    int v = blockIdx.x;
    if (!g_need1[v]) return;
    __shared__ int   scnt;
    __shared__ int   ssrc[DEG_CAP];
    __shared__ float se[DEG_CAP * 4];
    __shared__ float sh1[H1C];
    __shared__ float sg2[C2];
    __shared__ float sinv[4];
    int t = threadIdx.x;
    if (t == 0) scnt = 0;
    __syncthreads();
    int cb = min(g_cntB, EB_CAP);
    for (int j = t; j < cb; j += 256) {
        if (g_dstB[j] == v) {
            int p = atomicAdd(&scnt, 1);
            if (p < DEG_CAP - 1) ssrc[p] = g_srcB[j];
        }
    }
    __syncthreads();
    if (t == 0) {
        int p = min(scnt, DEG_CAP - 1);
        ssrc[p] = v;        // appended self-loop (matches reference)
        scnt = p + 1;
    }
    __syncthreads();
    int n = scnt;
    for (int idx = t; idx < n * 4; idx += 256) {
        int j = idx >> 2, hh = idx & 3;
        float e = g_as1[ssrc[j] * 4 + hh] + g_ad1[v * 4 + hh];
        se[j * 4 + hh] = (e > 0.f) ? e : 0.2f * e;   // leaky_relu(0.2)
    }
    __syncthreads();
    if (t < 4) {
        float m = -1e30f;
        for (int j = 0; j < n; j++) m = fmaxf(m, se[j * 4 + t]);
        float s = 0.f;
        for (int j = 0; j < n; j++) {
            float w = expf(se[j * 4 + t] - m);
            se[j * 4 + t] = w; s += w;
        }
        sinv[t] = 1.f / (s + 1e-16f);
    }
    __syncthreads();
    int hh = t >> 6;
    float acc = 0.f;
    for (int j = 0; j < n; j++)
        acc += se[j * 4 + hh] * g_h[(size_t)ssrc[j] * H1C + t];
    float h1 = acc * sinv[hh] + b1[t];
    sh1[t] = fmaxf(h1, 0.f);
    __syncthreads();
    if (t < C2) {
        float a = 0.f;
#pragma unroll 8
        for (int k = 0; k < H1C; k++) a += sh1[k] * W2[k * C2 + t];
        sg2[t] = a;
        g_g[(size_t)v * C2 + t] = a;
    }
    __syncthreads();
    if (t < 2) {
        const float* av = t ? a_dst2 : a_src2;
        float s = 0.f;
        for (int c = 0; c < C2; c++) s += sg2[c] * av[c];
        if (t) g_ad2[v] = s; else g_as2[v] = s;
    }
}

// Single block: layer-2 softmax aggregation at ball, relu, fc1+relu, fc2.
__global__ void k_final(const float* __restrict__ b2,
                        const float* __restrict__ fc1_w, const float* __restrict__ fc1_b,
                        const float* __restrict__ fc2_w, const float* __restrict__ fc2_b,
                        float* __restrict__ out, int ball) {
    __shared__ float w[SRCA_CAP + 1];
    __shared__ float so[C2];
    __shared__ float sz[32];
    __shared__ float sinv;
    int t = threadIdx.x;
    int n = min(g_cntA, SRCA_CAP);
    if (t == 0) {
        float adv = g_ad2[ball];
        float m = -1e30f;
        for (int j = 0; j <= n; j++) {
            int s = (j < n) ? g_srcA[j] : ball;          // last = self-loop
            float e = g_as2[s] + adv;
            e = (e > 0.f) ? e : 0.2f * e;
            w[j] = e;
            m = fmaxf(m, e);
        }
        float ssum = 0.f;
        for (int j = 0; j <= n; j++) { float ww = expf(w[j] - m); w[j] = ww; ssum += ww; }
        sinv = 1.f / (ssum + 1e-16f);
    }
    __syncthreads();
    if (t < C2) {
        float acc = 0.f;
        for (int j = 0; j <= n; j++) {
            int s = (j < n) ? g_srcA[j] : ball;
            acc += w[j] * g_g[(size_t)s * C2 + t];
        }
        float o = acc * sinv + b2[t];
        so[t] = fmaxf(o, 0.f);
    }
    __syncthreads();
    if (t < 32) {
        float a = fc1_b[t];
        for (int k = 0; k < C2; k++) a += so[k] * fc1_w[k * 32 + t];
        sz[t] = fmaxf(a, 0.f);
    }
    __syncthreads();
    if (t < 2) {
        float a = fc2_b[t];
        for (int k = 0; k < 32; k++) a += sz[k] * fc2_w[k * 2 + t];
        out[t] = a;
    }
}

extern "C" void kernel_launch(void* const* d_in, const int* in_sizes, int n_in,
                              void* d_out, int out_size) {
    const float* x      = (const float*)d_in[0];
    const int*   ei     = (const int*)d_in[1];   // int32: JAX x64-disabled coerces int64->int32
    const float* W1     = (const float*)d_in[2];
    const float* a_src1 = (const float*)d_in[3];
    const float* a_dst1 = (const float*)d_in[4];
    const float* b1     = (const float*)d_in[5];
    const float* W2     = (const float*)d_in[6];
    const float* a_src2 = (const float*)d_in[7];
    const float* a_dst2 = (const float*)d_in[8];
    const float* b2     = (const float*)d_in[9];
    const float* fc1_w  = (const float*)d_in[10];
    const float* fc1_b  = (const float*)d_in[11];
    const float* fc2_w  = (const float*)d_in[12];
    const float* fc2_b  = (const float*)d_in[13];

    int N = in_sizes[0] / FIN;   // 20000
    int E = in_sizes[1] / 2;     // 640000
    int ball = N - 1;

    k_reset<<<(N + 255) / 256, 256>>>(N);
    k_pass1<<<(E + 255) / 256, 256>>>(ei, E, ball, N);
    k_pass2<<<(E + 255) / 256, 256>>>(ei, E, N);
    k_feat <<<N, 256>>>(x, W1, a_src1, a_dst1);
    k_agg1 <<<N, 256>>>(b1, W2, a_src2, a_dst2);
    k_final<<<1, 64>>>(b2, fc1_w, fc1_b, fc2_w, fc2_b, (float*)d_out, ball);
}